// round 7
// baseline (speedup 1.0000x reference)
#include <cuda_runtime.h>
#include <cuda_fp16.h>
#include <math.h>
#include <stdint.h>

#define NB    8
#define NC    256
#define HID   512
#define NPIX  4096
#define NHEAD 8
#define DHEAD 64
#define NCHUNK 8
#define PART_LD 68
#define PART_BH (DHEAD * PART_LD)   // 4352

// ---------------- scratch ----------------
__device__ __align__(256) __half g_kvh[NB * 1024 * NPIX];               // rows 0-511 = exp(k), 512-1023 = v
__device__ __align__(256) __half g_cinh[NB * NC * NPIX];                // 16.8 MB
__device__ __align__(256) __half g_xh[NB * NC * NPIX];                  // 16.8 MB
__device__ __align__(256) __half g_wqh[HID * NC];
__device__ __align__(256) float g_wkv[1024 * NC];
__device__ __align__(256) float g_part[NCHUNK * NB * NHEAD * PART_BH];
__device__ __align__(256) float g_fold[NB * NC * HID];
__device__ __align__(256) float g_comb[NB * NC * NC];

// ---------------- helpers ----------------
__device__ __forceinline__ void mma_f16(float* d, const uint32_t* a, const uint32_t* b) {
    asm volatile(
        "mma.sync.aligned.m16n8k16.row.col.f32.f16.f16.f32 "
        "{%0,%1,%2,%3}, {%4,%5,%6,%7}, {%8,%9}, {%0,%1,%2,%3};"
        : "+f"(d[0]), "+f"(d[1]), "+f"(d[2]), "+f"(d[3])
        : "r"(a[0]), "r"(a[1]), "r"(a[2]), "r"(a[3]), "r"(b[0]), "r"(b[1]));
}

// ---------------- fp32 -> fp16 convert ----------------
__global__ void f2h_kernel(const float* __restrict__ in, __half* __restrict__ out, int n4)
{
    const int i = blockIdx.x * 256 + threadIdx.x;
    if (i < n4) {
        float4 v = ((const float4*)in)[i];
        __half2 a = __floats2half2_rn(v.x, v.y);
        __half2 b = __floats2half2_rn(v.z, v.w);
        uint2 u;
        u.x = *(uint32_t*)&a;
        u.y = *(uint32_t*)&b;
        ((uint2*)out)[i] = u;
    }
}

// ---------------- pack Wk;Wv ----------------
__global__ void pack_wkv(const float* __restrict__ Wk, const float* __restrict__ Wv,
                         float* __restrict__ Wkv)
{
    const int i = blockIdx.x * 256 + threadIdx.x;
    Wkv[i] = Wk[i];
    Wkv[HID * NC + i] = Wv[i];
}

// ---------------- fp16 mma GEMM, double-buffered, B operand pre-halved ----------------
// A: MxK rm fp32 (lda, sA; 0=shared). B: KxN rm HALF (ldb, sB).
// mode 0: C fp32 = alpha*A@B + bias[m].  mode 1: C half; rows m0<512 get exp().
// Tile 128x128x32, 256 threads, warps 2(m) x 4(n), warp tile 64x32.
__global__ __launch_bounds__(256, 2)
void mma_gemm_h(const float* __restrict__ A, long sA, int lda,
                const __half* __restrict__ B, long sB, int ldb,
                void* __restrict__ Cv, long sC, int ldc,
                const float* __restrict__ bias, int K, float alpha, int mode)
{
    __shared__ uint32_t As32[2][128][20];   // [m][k2] half2 along k
    __shared__ uint32_t Bs32[2][16][136];   // [k2][n] half2 along k

    const int bb = blockIdx.z;
    A += (size_t)bb * sA;
    B += (size_t)bb * sB;

    const int tid = threadIdx.x;
    const int wid = tid >> 5, lid = tid & 31;
    const int g = lid >> 2, t = lid & 3;
    const int wm = (wid >> 2) * 64, wn = (wid & 3) * 32;
    const int m0 = blockIdx.y * 128, n0 = blockIdx.x * 128;

    const int am = tid >> 1;          // A row 0..127
    const int as = tid & 1;
    const int bk = tid >> 3;          // B k-row 0..31
    const int bn8 = (tid & 7) * 16;   // B n start (16 halfs per thread)

    float acc[4][4][4];
    #pragma unroll
    for (int i = 0; i < 4; i++)
        #pragma unroll
        for (int j = 0; j < 4; j++)
            #pragma unroll
            for (int q = 0; q < 4; q++) acc[i][j][q] = 0.0f;

    const int KT = K >> 5;
    float4 aR[4];
    uint4 bR0, bR1;

    // prologue: load tile 0
    {
        const float* ap = A + (size_t)(m0 + am) * lda;
        #pragma unroll
        for (int p = 0; p < 4; p++)
            aR[p] = *(const float4*)(ap + (as + 2 * p) * 4);
        const __half* bp = B + (size_t)bk * ldb + n0 + bn8;
        bR0 = *(const uint4*)(bp);
        bR1 = *(const uint4*)(bp + 8);
    }
    // store tile 0 -> buf 0
    {
        #pragma unroll
        for (int p = 0; p < 4; p++) {
            const int k2 = (as + 2 * p) * 2;
            __half2 h0 = __floats2half2_rn(aR[p].x, aR[p].y);
            __half2 h1 = __floats2half2_rn(aR[p].z, aR[p].w);
            As32[0][am][k2 + 0] = *(uint32_t*)&h0;
            As32[0][am][k2 + 1] = *(uint32_t*)&h1;
        }
        __half* bsh = (__half*)&Bs32[0][0][0];
        const int base = (bk >> 1) * 272 + (bk & 1);
        const uint32_t w[8] = {bR0.x, bR0.y, bR0.z, bR0.w, bR1.x, bR1.y, bR1.z, bR1.w};
        #pragma unroll
        for (int q = 0; q < 8; q++) {
            __half2 h = *(__half2*)&w[q];
            bsh[base + 2 * (bn8 + 2 * q + 0)] = __low2half(h);
            bsh[base + 2 * (bn8 + 2 * q + 1)] = __high2half(h);
        }
    }
    __syncthreads();

    for (int kt = 0; kt < KT; kt++) {
        const int cur = kt & 1;
        const int nxt = cur ^ 1;
        const bool more = (kt + 1 < KT);

        if (more) {
            const int k0 = (kt + 1) << 5;
            const float* ap = A + (size_t)(m0 + am) * lda + k0;
            #pragma unroll
            for (int p = 0; p < 4; p++)
                aR[p] = *(const float4*)(ap + (as + 2 * p) * 4);
            const __half* bp = B + (size_t)(k0 + bk) * ldb + n0 + bn8;
            bR0 = *(const uint4*)(bp);
            bR1 = *(const uint4*)(bp + 8);
        }

        #pragma unroll
        for (int ks = 0; ks < 2; ks++) {
            const int kk2 = ks * 8;
            uint32_t af[4][4], bf[4][2];
            #pragma unroll
            for (int i = 0; i < 4; i++) {
                const int r = wm + i * 16 + g;
                af[i][0] = As32[cur][r][kk2 + t];
                af[i][1] = As32[cur][r + 8][kk2 + t];
                af[i][2] = As32[cur][r][kk2 + t + 4];
                af[i][3] = As32[cur][r + 8][kk2 + t + 4];
            }
            #pragma unroll
            for (int j = 0; j < 4; j++) {
                const int c = wn + j * 8 + g;
                bf[j][0] = Bs32[cur][kk2 + t][c];
                bf[j][1] = Bs32[cur][kk2 + t + 4][c];
            }
            #pragma unroll
            for (int i = 0; i < 4; i++)
                #pragma unroll
                for (int j = 0; j < 4; j++)
                    mma_f16(acc[i][j], af[i], bf[j]);
        }

        if (more) {
            #pragma unroll
            for (int p = 0; p < 4; p++) {
                const int k2 = (as + 2 * p) * 2;
                __half2 h0 = __floats2half2_rn(aR[p].x, aR[p].y);
                __half2 h1 = __floats2half2_rn(aR[p].z, aR[p].w);
                As32[nxt][am][k2 + 0] = *(uint32_t*)&h0;
                As32[nxt][am][k2 + 1] = *(uint32_t*)&h1;
            }
            __half* bsh = (__half*)&Bs32[nxt][0][0];
            const int base = (bk >> 1) * 272 + (bk & 1);
            const uint32_t w[8] = {bR0.x, bR0.y, bR0.z, bR0.w, bR1.x, bR1.y, bR1.z, bR1.w};
            #pragma unroll
            for (int q = 0; q < 8; q++) {
                __half2 h = *(__half2*)&w[q];
                bsh[base + 2 * (bn8 + 2 * q + 0)] = __low2half(h);
                bsh[base + 2 * (bn8 + 2 * q + 1)] = __high2half(h);
            }
        }
        __syncthreads();
    }

    if (mode == 0) {
        float* C = (float*)Cv + (size_t)bb * sC;
        #pragma unroll
        for (int i = 0; i < 4; i++) {
            const int r0 = m0 + wm + i * 16 + g;
            const int r1 = r0 + 8;
            const float bi0 = bias ? bias[r0] : 0.0f;
            const float bi1 = bias ? bias[r1] : 0.0f;
            #pragma unroll
            for (int j = 0; j < 4; j++) {
                const int col = n0 + wn + j * 8 + 2 * t;
                float2 o0 = make_float2(acc[i][j][0] * alpha + bi0, acc[i][j][1] * alpha + bi0);
                float2 o1 = make_float2(acc[i][j][2] * alpha + bi1, acc[i][j][3] * alpha + bi1);
                *(float2*)(C + (size_t)r0 * ldc + col) = o0;
                *(float2*)(C + (size_t)r1 * ldc + col) = o1;
            }
        }
    } else {
        __half* C = (__half*)Cv + (size_t)bb * sC;
        const bool doexp = (m0 < 512);
        #pragma unroll
        for (int i = 0; i < 4; i++) {
            const int r0 = m0 + wm + i * 16 + g;
            const int r1 = r0 + 8;
            #pragma unroll
            for (int j = 0; j < 4; j++) {
                const int col = n0 + wn + j * 8 + 2 * t;
                float4 v = make_float4(acc[i][j][0], acc[i][j][1], acc[i][j][2], acc[i][j][3]);
                if (doexp) {
                    v.x = expf(v.x); v.y = expf(v.y); v.z = expf(v.z); v.w = expf(v.w);
                }
                *(__half2*)(C + (size_t)r0 * ldc + col) = __floats2half2_rn(v.x, v.y);
                *(__half2*)(C + (size_t)r1 * ldc + col) = __floats2half2_rn(v.z, v.w);
            }
        }
    }
}

// ---------------- ctx partial via fp16 mma (NT, data already half) ----------------
__global__ __launch_bounds__(256)
void ctx_partial_kernel(const __half* __restrict__ KVh, float* __restrict__ part)
{
    const int bh = blockIdx.x;
    const int ch = blockIdx.y;
    const int b = bh >> 3, h = bh & 7;
    const __half* kp = KVh + (size_t)b * 1024 * NPIX + (size_t)(h * 64) * NPIX;
    const __half* vp = KVh + (size_t)b * 1024 * NPIX + (size_t)(512 + h * 64) * NPIX;

    __shared__ uint32_t As32[64][20];
    __shared__ uint32_t Bs32[64][20];

    const int tid = threadIdx.x;
    const int wid = tid >> 5, lid = tid & 31;
    const int g = lid >> 2, t = lid & 3;
    const int wm = (wid & 3) * 16, wn = (wid >> 2) * 32;

    const int d  = tid >> 2;
    const int m8 = (tid & 3) << 3;
    const int w0 = m8 >> 1;

    float acc[4][4];
    #pragma unroll
    for (int j = 0; j < 4; j++)
        #pragma unroll
        for (int q = 0; q < 4; q++) acc[j][q] = 0.0f;

    float es = 0.0f;
    const int mbeg = ch * (NPIX / NCHUNK);
    const int mend = mbeg + (NPIX / NCHUNK);

    for (int m0 = mbeg; m0 < mend; m0 += 32) {
        uint4 ka = *(const uint4*)(kp + (size_t)d * NPIX + m0 + m8);
        uint4 va = *(const uint4*)(vp + (size_t)d * NPIX + m0 + m8);
        As32[d][w0 + 0] = ka.x; As32[d][w0 + 1] = ka.y;
        As32[d][w0 + 2] = ka.z; As32[d][w0 + 3] = ka.w;
        Bs32[d][w0 + 0] = va.x; Bs32[d][w0 + 1] = va.y;
        Bs32[d][w0 + 2] = va.z; Bs32[d][w0 + 3] = va.w;
        float2 f0 = __half22float2(*(__half2*)&ka.x);
        float2 f1 = __half22float2(*(__half2*)&ka.y);
        float2 f2 = __half22float2(*(__half2*)&ka.z);
        float2 f3 = __half22float2(*(__half2*)&ka.w);
        es += (f0.x + f0.y) + (f1.x + f1.y) + ((f2.x + f2.y) + (f3.x + f3.y));

        __syncthreads();

        #pragma unroll
        for (int ks = 0; ks < 2; ks++) {
            const int kk2 = ks * 8;
            uint32_t af[4], bf[4][2];
            af[0] = As32[wm + g][kk2 + t];
            af[1] = As32[wm + g + 8][kk2 + t];
            af[2] = As32[wm + g][kk2 + t + 4];
            af[3] = As32[wm + g + 8][kk2 + t + 4];
            #pragma unroll
            for (int j = 0; j < 4; j++) {
                const int c = wn + j * 8 + g;
                bf[j][0] = Bs32[c][kk2 + t];
                bf[j][1] = Bs32[c][kk2 + t + 4];
            }
            #pragma unroll
            for (int j = 0; j < 4; j++)
                mma_f16(acc[j], af, bf[j]);
        }
        __syncthreads();
    }

    float* cp = part + ((size_t)ch * 64 + bh) * PART_BH;
    const int r0 = wm + g, r1 = wm + g + 8;
    #pragma unroll
    for (int j = 0; j < 4; j++) {
        const int c = wn + j * 8 + 2 * t;
        cp[r0 * PART_LD + c]     = acc[j][0];
        cp[r0 * PART_LD + c + 1] = acc[j][1];
        cp[r1 * PART_LD + c]     = acc[j][2];
        cp[r1 * PART_LD + c + 1] = acc[j][3];
    }

    es += __shfl_xor_sync(0xffffffffu, es, 1);
    es += __shfl_xor_sync(0xffffffffu, es, 2);
    if ((tid & 3) == 0) cp[d * PART_LD + 64] = es;
}

// ---------------- reduce partials, normalize, fold Wo (4-way d split) ----------------
__global__ void fold_kernel(const float* __restrict__ Wo, const float* __restrict__ part,
                            float* __restrict__ fold)
{
    const int bh = blockIdx.x;
    const int qd = blockIdx.y;
    const int b = bh >> 3, h = bh & 7;
    const int dd0 = qd * 16;

    __shared__ float cs[16][64];
    __shared__ float Sd[16];

    const int tid = threadIdx.x;
    if (tid < 16) {
        float s = 0.0f;
        #pragma unroll
        for (int ch = 0; ch < NCHUNK; ch++)
            s += part[((size_t)ch * 64 + bh) * PART_BH + (dd0 + tid) * PART_LD + 64];
        Sd[tid] = 1.0f / s;
    }
    __syncthreads();

    {
        const int dd = tid >> 4, e4 = (tid & 15) * 4;
        float4 s = make_float4(0.f, 0.f, 0.f, 0.f);
        #pragma unroll
        for (int ch = 0; ch < NCHUNK; ch++) {
            float4 p = *(const float4*)(part + ((size_t)ch * 64 + bh) * PART_BH + (dd0 + dd) * PART_LD + e4);
            s.x += p.x; s.y += p.y; s.z += p.z; s.w += p.w;
        }
        const float iv = Sd[dd];
        cs[dd][e4 + 0] = s.x * iv;
        cs[dd][e4 + 1] = s.y * iv;
        cs[dd][e4 + 2] = s.z * iv;
        cs[dd][e4 + 3] = s.w * iv;
    }
    __syncthreads();

    const int o = tid;
    float4 w[16];
    #pragma unroll
    for (int e = 0; e < 16; e++)
        w[e] = *(const float4*)(Wo + (size_t)o * HID + h * 64 + e * 4);

    float* fp = fold + ((size_t)b * NC + o) * HID + h * 64 + dd0;
    #pragma unroll
    for (int dd = 0; dd < 16; dd++) {
        float s = 0.0f;
        #pragma unroll
        for (int e = 0; e < 16; e++) {
            float4 c = *(const float4*)&cs[dd][e * 4];
            s += w[e].x * c.x + w[e].y * c.y + w[e].z * c.z + w[e].w * c.w;
        }
        fp[dd] = s;
    }
}

// ---------------- launch ----------------
extern "C" void kernel_launch(void* const* d_in, const int* in_sizes, int n_in,
                              void* d_out, int out_size)
{
    const float* x    = (const float*)d_in[0];
    const float* cin  = (const float*)d_in[1];
    const float* Wq   = (const float*)d_in[2];
    const float* Wk   = (const float*)d_in[3];
    const float* Wv   = (const float*)d_in[4];
    const float* Wo   = (const float*)d_in[5];
    const float* bo   = (const float*)d_in[6];
    float* out = (float*)d_out;

    __half *kvh, *cinh, *xh, *wqh;
    float *wkv, *pt, *fd, *cb;
    cudaGetSymbolAddress((void**)&kvh, g_kvh);
    cudaGetSymbolAddress((void**)&cinh, g_cinh);
    cudaGetSymbolAddress((void**)&xh, g_xh);
    cudaGetSymbolAddress((void**)&wqh, g_wqh);
    cudaGetSymbolAddress((void**)&wkv, g_wkv);
    cudaGetSymbolAddress((void**)&pt, g_part);
    cudaGetSymbolAddress((void**)&fd, g_fold);
    cudaGetSymbolAddress((void**)&cb, g_comb);

    const float scale = 0.125f;
    const int nbig = NB * NC * NPIX / 4;   // 2097152

    f2h_kernel<<<nbig / 256, 256>>>(cin, cinh, nbig);
    f2h_kernel<<<nbig / 256, 256>>>(x, xh, nbig);
    f2h_kernel<<<HID * NC / 4 / 256, 256>>>(Wq, wqh, HID * NC / 4);
    pack_wkv<<<HID * NC / 256, 256>>>(Wk, Wv, wkv);

    // kv = Wkv @ cin -> half, exp on k rows  (M=1024, N=4096, K=256 per batch)
    dim3 gproj(NPIX / 128, 1024 / 128, NB);
    mma_gemm_h<<<gproj, 256>>>(wkv, 0, NC, cinh, (long)NC * NPIX, NPIX,
                               kvh, (long)1024 * NPIX, NPIX, nullptr, NC, 1.0f, 1);

    // ctx partials
    dim3 gctx(NB * NHEAD, NCHUNK);
    ctx_partial_kernel<<<gctx, 256>>>(kvh, pt);

    // reduce + normalize + fold Wo
    dim3 gfold(NB * NHEAD, 4);
    fold_kernel<<<gfold, 256>>>(Wo, pt, fd);

    // comb[b] = fold[b] @ (scale*Wq)  (M=256, N=256, K=512)
    dim3 gcomb(NC / 128, NC / 128, NB);
    mma_gemm_h<<<gcomb, 256>>>(fd, (long)NC * HID, HID, wqh, 0, NC,
                               cb, (long)NC * NC, NC, nullptr, HID, scale, 0);

    // out = comb @ x + bo  (M=256, N=4096, K=256)
    dim3 gfin(NPIX / 128, NC / 128, NB);
    mma_gemm_h<<<gfin, 256>>>(cb, (long)NC * NC, NC, xh, (long)NC * NPIX, NPIX,
                              out, (long)NC * NPIX, NPIX, bo, NC, 1.0f, 0);
}

// round 8
// speedup vs baseline: 1.2621x; 1.2621x over previous
#include <cuda_runtime.h>
#include <cuda_fp16.h>
#include <math.h>
#include <stdint.h>

#define NB    8
#define NC    256
#define HID   512
#define NPIX  4096
#define NHEAD 8
#define DHEAD 64
#define NCHUNK 8
#define PART_LD 68
#define PART_BH (DHEAD * PART_LD)   // 4352

// ---------------- scratch ----------------
__device__ __align__(256) __half g_kvh[NB * 1024 * NPIX];   // rows 0-511 = exp(k), 512-1023 = v
__device__ __align__(256) __half g_wkvh[1024 * NC];
__device__ __align__(256) __half g_wqh[HID * NC];
__device__ __align__(256) float g_part[NCHUNK * NB * NHEAD * PART_BH];
__device__ __align__(256) float g_fold[NB * NC * HID];
__device__ __align__(256) float g_comb[NB * NC * NC];

// ---------------- helpers ----------------
__device__ __forceinline__ void mma_f16(float* d, const uint32_t* a, const uint32_t* b) {
    asm volatile(
        "mma.sync.aligned.m16n8k16.row.col.f32.f16.f16.f32 "
        "{%0,%1,%2,%3}, {%4,%5,%6,%7}, {%8,%9}, {%0,%1,%2,%3};"
        : "+f"(d[0]), "+f"(d[1]), "+f"(d[2]), "+f"(d[3])
        : "r"(a[0]), "r"(a[1]), "r"(a[2]), "r"(a[3]), "r"(b[0]), "r"(b[1]));
}

// ---------------- pack weights to half: Wkv = [Wk;Wv], Wq ----------------
__global__ void pack_w(const float* __restrict__ Wk, const float* __restrict__ Wv,
                       const float* __restrict__ Wq,
                       __half* __restrict__ Wkvh, __half* __restrict__ Wqh)
{
    const int i = blockIdx.x * 256 + threadIdx.x;   // 0 .. 512*256-1
    Wkvh[i] = __float2half_rn(Wk[i]);
    Wkvh[HID * NC + i] = __float2half_rn(Wv[i]);
    Wqh[i] = __float2half_rn(Wq[i]);
}

// ---------------- fp16 mma GEMM, double-buffered, templated operand types ----------------
// A: MxK rm (lda, sA; 0 => shared across batch). B: KxN rm (ldb, sB).
// MODE 0: C fp32 = alpha*A@B + bias[m].  MODE 1: C half; rows with m0<512 get exp().
// Tile 128x128x32, 256 threads, warps 2(m) x 4(n), warp tile 64x32.
template<int AHALF, int BHALF, int MODE>
__global__ __launch_bounds__(256, 2)
void mma_gemm_t(const void* __restrict__ Av, long sA, int lda,
                const void* __restrict__ Bv, long sB, int ldb,
                void* __restrict__ Cv, long sC, int ldc,
                const float* __restrict__ bias, int K, float alpha)
{
    __shared__ uint32_t As32[2][128][20];   // [m][k2], half2 along k
    __shared__ uint32_t Bs32[2][16][136];   // [k2][n], half2 along k

    const int bb = blockIdx.z;
    const float*  Af = (const float*)Av + (AHALF ? 0 : (size_t)bb * sA);
    const __half* Ah = (const __half*)Av + (AHALF ? (size_t)bb * sA : 0);
    const float*  Bf = (const float*)Bv + (BHALF ? 0 : (size_t)bb * sB);
    const __half* Bh = (const __half*)Bv + (BHALF ? (size_t)bb * sB : 0);

    const int tid = threadIdx.x;
    const int wid = tid >> 5, lid = tid & 31;
    const int g = lid >> 2, t = lid & 3;
    const int wm = (wid >> 2) * 64, wn = (wid & 3) * 32;
    const int m0 = blockIdx.y * 128, n0 = blockIdx.x * 128;

    const int am = tid >> 1;          // A row 0..127
    const int as = tid & 1;           // A k-half selector
    const int bk = tid >> 3;          // B k-row 0..31
    const int bn8 = (tid & 7) * 16;   // B n start (16 elems per thread)

    float acc[4][4][4];
    #pragma unroll
    for (int i = 0; i < 4; i++)
        #pragma unroll
        for (int j = 0; j < 4; j++)
            #pragma unroll
            for (int q = 0; q < 4; q++) acc[i][j][q] = 0.0f;

    const int KT = K >> 5;

    // staging registers
    float4 aRf[4];
    uint4  aRh0, aRh1;
    float4 bRf[4];
    uint4  bRh0, bRh1;

    // ---- load tile kt into regs ----
    auto loadA = [&](int k0) {
        if (AHALF) {
            const __half* ap = Ah + (size_t)(m0 + am) * lda + k0 + as * 16;
            aRh0 = *(const uint4*)(ap);
            aRh1 = *(const uint4*)(ap + 8);
        } else {
            const float* ap = Af + (size_t)(m0 + am) * lda + k0;
            #pragma unroll
            for (int p = 0; p < 4; p++)
                aRf[p] = *(const float4*)(ap + (as + 2 * p) * 4);
        }
    };
    auto loadB = [&](int k0) {
        if (BHALF) {
            const __half* bp = Bh + (size_t)(k0 + bk) * ldb + n0 + bn8;
            bRh0 = *(const uint4*)(bp);
            bRh1 = *(const uint4*)(bp + 8);
        } else {
            const float* bp = Bf + (size_t)(k0 + bk) * ldb + n0;
            #pragma unroll
            for (int p = 0; p < 4; p++)
                bRf[p] = *(const float4*)(bp + bn8 / 4 + 32 * p);
        }
    };
    auto storeA = [&](int buf) {
        if (AHALF) {
            const int k2 = as * 8;
            As32[buf][am][k2 + 0] = aRh0.x; As32[buf][am][k2 + 1] = aRh0.y;
            As32[buf][am][k2 + 2] = aRh0.z; As32[buf][am][k2 + 3] = aRh0.w;
            As32[buf][am][k2 + 4] = aRh1.x; As32[buf][am][k2 + 5] = aRh1.y;
            As32[buf][am][k2 + 6] = aRh1.z; As32[buf][am][k2 + 7] = aRh1.w;
        } else {
            #pragma unroll
            for (int p = 0; p < 4; p++) {
                const int k2 = (as + 2 * p) * 2;
                __half2 h0 = __floats2half2_rn(aRf[p].x, aRf[p].y);
                __half2 h1 = __floats2half2_rn(aRf[p].z, aRf[p].w);
                As32[buf][am][k2 + 0] = *(uint32_t*)&h0;
                As32[buf][am][k2 + 1] = *(uint32_t*)&h1;
            }
        }
    };
    auto storeB = [&](int buf) {
        __half* bsh = (__half*)&Bs32[buf][0][0];
        const int base = (bk >> 1) * 272 + (bk & 1);
        if (BHALF) {
            const uint32_t w[8] = {bRh0.x, bRh0.y, bRh0.z, bRh0.w, bRh1.x, bRh1.y, bRh1.z, bRh1.w};
            #pragma unroll
            for (int q = 0; q < 8; q++) {
                __half2 h = *(__half2*)&w[q];
                bsh[base + 2 * (bn8 + 2 * q + 0)] = __low2half(h);
                bsh[base + 2 * (bn8 + 2 * q + 1)] = __high2half(h);
            }
        } else {
            #pragma unroll
            for (int p = 0; p < 4; p++) {
                const int nf = (bn8 / 4) + 32 * p;   // matches loadB layout: 4 floats at nf*? 
                bsh[base + 2 * (nf * 1 + 0)] = __float2half_rn(bRf[p].x);
                bsh[base + 2 * (nf + 1)] = __float2half_rn(bRf[p].y);
                bsh[base + 2 * (nf + 2)] = __float2half_rn(bRf[p].z);
                bsh[base + 2 * (nf + 3)] = __float2half_rn(bRf[p].w);
            }
        }
    };

    loadA(0);
    loadB(0);
    storeA(0);
    storeB(0);
    __syncthreads();

    for (int kt = 0; kt < KT; kt++) {
        const int cur = kt & 1;
        const int nxt = cur ^ 1;
        const bool more = (kt + 1 < KT);

        if (more) {
            loadA((kt + 1) << 5);
            loadB((kt + 1) << 5);
        }

        #pragma unroll
        for (int ks = 0; ks < 2; ks++) {
            const int kk2 = ks * 8;
            uint32_t af[4][4], bf[4][2];
            #pragma unroll
            for (int i = 0; i < 4; i++) {
                const int r = wm + i * 16 + g;
                af[i][0] = As32[cur][r][kk2 + t];
                af[i][1] = As32[cur][r + 8][kk2 + t];
                af[i][2] = As32[cur][r][kk2 + t + 4];
                af[i][3] = As32[cur][r + 8][kk2 + t + 4];
            }
            #pragma unroll
            for (int j = 0; j < 4; j++) {
                const int c = wn + j * 8 + g;
                bf[j][0] = Bs32[cur][kk2 + t][c];
                bf[j][1] = Bs32[cur][kk2 + t + 4][c];
            }
            #pragma unroll
            for (int i = 0; i < 4; i++)
                #pragma unroll
                for (int j = 0; j < 4; j++)
                    mma_f16(acc[i][j], af[i], bf[j]);
        }

        if (more) {
            storeA(nxt);
            storeB(nxt);
        }
        __syncthreads();
    }

    if (MODE == 0) {
        float* C = (float*)Cv + (size_t)bb * sC;
        #pragma unroll
        for (int i = 0; i < 4; i++) {
            const int r0 = m0 + wm + i * 16 + g;
            const int r1 = r0 + 8;
            const float bi0 = bias ? bias[r0] : 0.0f;
            const float bi1 = bias ? bias[r1] : 0.0f;
            #pragma unroll
            for (int j = 0; j < 4; j++) {
                const int col = n0 + wn + j * 8 + 2 * t;
                float2 o0 = make_float2(acc[i][j][0] * alpha + bi0, acc[i][j][1] * alpha + bi0);
                float2 o1 = make_float2(acc[i][j][2] * alpha + bi1, acc[i][j][3] * alpha + bi1);
                *(float2*)(C + (size_t)r0 * ldc + col) = o0;
                *(float2*)(C + (size_t)r1 * ldc + col) = o1;
            }
        }
    } else {
        __half* C = (__half*)Cv + (size_t)bb * sC;
        const bool doexp = (m0 < 512);
        #pragma unroll
        for (int i = 0; i < 4; i++) {
            const int r0 = m0 + wm + i * 16 + g;
            const int r1 = r0 + 8;
            #pragma unroll
            for (int j = 0; j < 4; j++) {
                const int col = n0 + wn + j * 8 + 2 * t;
                float4 v = make_float4(acc[i][j][0], acc[i][j][1], acc[i][j][2], acc[i][j][3]);
                if (doexp) {
                    v.x = expf(v.x); v.y = expf(v.y); v.z = expf(v.z); v.w = expf(v.w);
                }
                *(__half2*)(C + (size_t)r0 * ldc + col) = __floats2half2_rn(v.x, v.y);
                *(__half2*)(C + (size_t)r1 * ldc + col) = __floats2half2_rn(v.z, v.w);
            }
        }
    }
}

// ---------------- ctx partial via fp16 mma (NT, data already half) ----------------
__global__ __launch_bounds__(256)
void ctx_partial_kernel(const __half* __restrict__ KVh, float* __restrict__ part)
{
    const int bh = blockIdx.x;
    const int ch = blockIdx.y;
    const int b = bh >> 3, h = bh & 7;
    const __half* kp = KVh + (size_t)b * 1024 * NPIX + (size_t)(h * 64) * NPIX;
    const __half* vp = KVh + (size_t)b * 1024 * NPIX + (size_t)(512 + h * 64) * NPIX;

    __shared__ uint32_t As32[64][20];
    __shared__ uint32_t Bs32[64][20];

    const int tid = threadIdx.x;
    const int wid = tid >> 5, lid = tid & 31;
    const int g = lid >> 2, t = lid & 3;
    const int wm = (wid & 3) * 16, wn = (wid >> 2) * 32;

    const int d  = tid >> 2;
    const int m8 = (tid & 3) << 3;
    const int w0 = m8 >> 1;

    float acc[4][4];
    #pragma unroll
    for (int j = 0; j < 4; j++)
        #pragma unroll
        for (int q = 0; q < 4; q++) acc[j][q] = 0.0f;

    float es = 0.0f;
    const int mbeg = ch * (NPIX / NCHUNK);
    const int mend = mbeg + (NPIX / NCHUNK);

    for (int m0 = mbeg; m0 < mend; m0 += 32) {
        uint4 ka = *(const uint4*)(kp + (size_t)d * NPIX + m0 + m8);
        uint4 va = *(const uint4*)(vp + (size_t)d * NPIX + m0 + m8);
        As32[d][w0 + 0] = ka.x; As32[d][w0 + 1] = ka.y;
        As32[d][w0 + 2] = ka.z; As32[d][w0 + 3] = ka.w;
        Bs32[d][w0 + 0] = va.x; Bs32[d][w0 + 1] = va.y;
        Bs32[d][w0 + 2] = va.z; Bs32[d][w0 + 3] = va.w;
        float2 f0 = __half22float2(*(__half2*)&ka.x);
        float2 f1 = __half22float2(*(__half2*)&ka.y);
        float2 f2 = __half22float2(*(__half2*)&ka.z);
        float2 f3 = __half22float2(*(__half2*)&ka.w);
        es += (f0.x + f0.y) + (f1.x + f1.y) + ((f2.x + f2.y) + (f3.x + f3.y));

        __syncthreads();

        #pragma unroll
        for (int ks = 0; ks < 2; ks++) {
            const int kk2 = ks * 8;
            uint32_t af[4], bf[4][2];
            af[0] = As32[wm + g][kk2 + t];
            af[1] = As32[wm + g + 8][kk2 + t];
            af[2] = As32[wm + g][kk2 + t + 4];
            af[3] = As32[wm + g + 8][kk2 + t + 4];
            #pragma unroll
            for (int j = 0; j < 4; j++) {
                const int c = wn + j * 8 + g;
                bf[j][0] = Bs32[c][kk2 + t];
                bf[j][1] = Bs32[c][kk2 + t + 4];
            }
            #pragma unroll
            for (int j = 0; j < 4; j++)
                mma_f16(acc[j], af, bf[j]);
        }
        __syncthreads();
    }

    float* cp = part + ((size_t)ch * 64 + bh) * PART_BH;
    const int r0 = wm + g, r1 = wm + g + 8;
    #pragma unroll
    for (int j = 0; j < 4; j++) {
        const int c = wn + j * 8 + 2 * t;
        cp[r0 * PART_LD + c]     = acc[j][0];
        cp[r0 * PART_LD + c + 1] = acc[j][1];
        cp[r1 * PART_LD + c]     = acc[j][2];
        cp[r1 * PART_LD + c + 1] = acc[j][3];
    }

    es += __shfl_xor_sync(0xffffffffu, es, 1);
    es += __shfl_xor_sync(0xffffffffu, es, 2);
    if ((tid & 3) == 0) cp[d * PART_LD + 64] = es;
}

// ---------------- reduce partials, normalize, fold Wo (4-way d split) ----------------
__global__ void fold_kernel(const float* __restrict__ Wo, const float* __restrict__ part,
                            float* __restrict__ fold)
{
    const int bh = blockIdx.x;
    const int qd = blockIdx.y;
    const int b = bh >> 3, h = bh & 7;
    const int dd0 = qd * 16;

    __shared__ float cs[16][64];
    __shared__ float Sd[16];

    const int tid = threadIdx.x;
    if (tid < 16) {
        float s = 0.0f;
        #pragma unroll
        for (int ch = 0; ch < NCHUNK; ch++)
            s += part[((size_t)ch * 64 + bh) * PART_BH + (dd0 + tid) * PART_LD + 64];
        Sd[tid] = 1.0f / s;
    }
    __syncthreads();

    {
        const int dd = tid >> 4, e4 = (tid & 15) * 4;
        float4 s = make_float4(0.f, 0.f, 0.f, 0.f);
        #pragma unroll
        for (int ch = 0; ch < NCHUNK; ch++) {
            float4 p = *(const float4*)(part + ((size_t)ch * 64 + bh) * PART_BH + (dd0 + dd) * PART_LD + e4);
            s.x += p.x; s.y += p.y; s.z += p.z; s.w += p.w;
        }
        const float iv = Sd[dd];
        cs[dd][e4 + 0] = s.x * iv;
        cs[dd][e4 + 1] = s.y * iv;
        cs[dd][e4 + 2] = s.z * iv;
        cs[dd][e4 + 3] = s.w * iv;
    }
    __syncthreads();

    const int o = tid;
    float4 w[16];
    #pragma unroll
    for (int e = 0; e < 16; e++)
        w[e] = *(const float4*)(Wo + (size_t)o * HID + h * 64 + e * 4);

    float* fp = fold + ((size_t)b * NC + o) * HID + h * 64 + dd0;
    #pragma unroll
    for (int dd = 0; dd < 16; dd++) {
        float s = 0.0f;
        #pragma unroll
        for (int e = 0; e < 16; e++) {
            float4 c = *(const float4*)&cs[dd][e * 4];
            s += w[e].x * c.x + w[e].y * c.y + w[e].z * c.z + w[e].w * c.w;
        }
        fp[dd] = s;
    }
}

// ---------------- launch ----------------
extern "C" void kernel_launch(void* const* d_in, const int* in_sizes, int n_in,
                              void* d_out, int out_size)
{
    const float* x    = (const float*)d_in[0];
    const float* cin  = (const float*)d_in[1];
    const float* Wq   = (const float*)d_in[2];
    const float* Wk   = (const float*)d_in[3];
    const float* Wv   = (const float*)d_in[4];
    const float* Wo   = (const float*)d_in[5];
    const float* bo   = (const float*)d_in[6];
    float* out = (float*)d_out;

    __half *kvh, *wkvh, *wqh;
    float *pt, *fd, *cb;
    cudaGetSymbolAddress((void**)&kvh, g_kvh);
    cudaGetSymbolAddress((void**)&wkvh, g_wkvh);
    cudaGetSymbolAddress((void**)&wqh, g_wqh);
    cudaGetSymbolAddress((void**)&pt, g_part);
    cudaGetSymbolAddress((void**)&fd, g_fold);
    cudaGetSymbolAddress((void**)&cb, g_comb);

    const float scale = 0.125f;

    pack_w<<<HID * NC / 256, 256>>>(Wk, Wv, Wq, wkvh, wqh);

    // kv = Wkv @ cin -> half with exp on k rows (M=1024, N=4096, K=256 per batch)
    dim3 gproj(NPIX / 128, 1024 / 128, NB);
    mma_gemm_t<1, 0, 1><<<gproj, 256>>>(wkvh, 0, NC, cin, (long)NC * NPIX, NPIX,
                                        kvh, (long)1024 * NPIX, NPIX, nullptr, NC, 1.0f);

    // ctx partials
    dim3 gctx(NB * NHEAD, NCHUNK);
    ctx_partial_kernel<<<gctx, 256>>>(kvh, pt);

    // reduce + normalize + fold Wo
    dim3 gfold(NB * NHEAD, 4);
    fold_kernel<<<gfold, 256>>>(Wo, pt, fd);

    // comb[b] = fold[b] @ (scale*Wq)  (M=256, N=256, K=512)
    dim3 gcomb(NC / 128, NC / 128, NB);
    mma_gemm_t<0, 1, 0><<<gcomb, 256>>>(fd, (long)NC * HID, HID, wqh, 0, NC,
                                        cb, (long)NC * NC, NC, nullptr, HID, scale);

    // out = comb @ x + bo  (M=256, N=4096, K=256)
    dim3 gfin(NPIX / 128, NC / 128, NB);
    mma_gemm_t<0, 0, 0><<<gfin, 256>>>(cb, (long)NC * NC, NC, x, (long)NC * NPIX, NPIX,
                                       out, (long)NC * NPIX, NPIX, bo, NC, 1.0f);
}